// round 10
// baseline (speedup 1.0000x reference)
#include <cuda_runtime.h>
#include <cuda_bf16.h>
#include <stdint.h>
#include <math.h>

// Problem constants
#define B_      32
#define CIN     512
#define HW      4096          // 64*64
#define VD      16
#define NCHUNK1 8             // pixel chunks per image in k_root (512 px each)
#define NCHUNK3 16            // chunks per image in k_mant (256 px each)

// Scratch (device globals; no allocation allowed)
__device__ float g_feats0[B_ * VD * HW];          // 8 MB, layout [b][k][pixel]
__device__ float g_pool_part[B_ * NCHUNK1 * VD];  // per-chunk pooled partial sums
__device__ float g_M[B_ * VD * VD];               // composed path matrix per batch
__device__ float g_cvec[B_ * VD];                 // composed path bias per batch
__device__ float g_mpart[B_ * NCHUNK3];           // mantissa partial sums
__device__ int   g_ctr_root;                      // k_root completion counter
__device__ int   g_ctr_mant;                      // k_mant completion counter

__constant__ int c_off[4] = {0, 2, 5, 9};         // LEVEL_OFFSETS

// ---- f32x2 packed helpers (Blackwell FFMA2, PTX-only) ----------------------
__device__ __forceinline__ unsigned long long pack2(float lo, float hi) {
    unsigned long long r;
    asm("mov.b64 %0, {%1, %2};" : "=l"(r) : "f"(lo), "f"(hi));
    return r;
}
__device__ __forceinline__ void fma2(unsigned long long& d,
                                     unsigned long long a,
                                     unsigned long long b) {
    asm("fma.rn.f32x2 %0, %1, %2, %0;" : "+l"(d) : "l"(a), "l"(b));
}
__device__ __forceinline__ void unpack2(unsigned long long p, float& lo, float& hi) {
    asm("mov.b64 {%0, %1}, %2;" : "=f"(lo), "=f"(hi) : "l"(p));
}

// ---------------------------------------------------------------------------
// Binomial tree on pooled vectors (runs in ONE block of >=256 threads).
// Emits class_logits + selected_class, composes the path matrix/bias.
// ---------------------------------------------------------------------------
__device__ void tree_body(const float* __restrict__ lw,
                          const float* __restrict__ lb,
                          float* __restrict__ out, int tid)
{
    __shared__ float P[5][VD], Pn[5][VD];
    __shared__ float norms[5];
    __shared__ int   choice[5][5];
    __shared__ int   path[5];
    __shared__ float M[VD * VD], cv[VD];

    if (tid < VD) {
        float s = 0.f;
        // sum over all batches' partials handled per-b below; here per-b loop
    }
    for (int b = 0; b < B_; b++) {
        if (tid < VD) {
            float s = 0.f;
#pragma unroll
            for (int c = 0; c < NCHUNK1; c++)
                s += g_pool_part[(b * NCHUNK1 + c) * VD + tid];
            P[0][tid] = s * (1.0f / (float)HW);
        }
        __syncthreads();

        int ncur = 1;
        for (int level = 1; level <= 4; level++) {
            const int off = c_off[level - 1];
            const int nn  = level + 1;
            if (tid < ncur) {
                float s = 0.f;
#pragma unroll
                for (int k = 0; k < VD; k++) s += P[tid][k] * P[tid][k];
                norms[tid] = sqrtf(s);
            }
            __syncthreads();
            if (tid < nn) {
                int pl = tid - 1; if (pl < 0) pl = 0;
                int pr = tid;     if (pr > level - 1) pr = level - 1;
                int ch = pl;
                if (pl != pr && norms[pr] > norms[pl]) ch = pr;
                choice[level][tid] = ch;
            }
            __syncthreads();
            if (tid < nn * VD) {
                int node = tid >> 4, i = tid & 15;
                const float* W = lw + (size_t)(off + node) * VD * VD + i * VD;
                const float* par = P[choice[level][node]];
                float s = lb[(off + node) * VD + i];
#pragma unroll
                for (int k = 0; k < VD; k++) s = fmaf(W[k], par[k], s);
                Pn[node][i] = s;
            }
            __syncthreads();
            if (tid < nn * VD) P[tid >> 4][tid & 15] = Pn[tid >> 4][tid & 15];
            __syncthreads();
            ncur = nn;
        }

        if (tid < 5) {
            float s = 0.f;
#pragma unroll
            for (int k = 0; k < VD; k++) s += P[tid][k] * P[tid][k];
            norms[tid] = sqrtf(s);
            out[b * 5 + tid] = norms[tid];      // class_logits
        }
        __syncthreads();
        if (tid == 0) {
            int best = 0; float bv = norms[0];
            for (int j = 1; j < 5; j++)
                if (norms[j] > bv) { bv = norms[j]; best = j; }
            out[192 + b] = (float)best;         // selected_class
            path[4] = best;
            path[3] = choice[4][path[4]];
            path[2] = choice[3][path[3]];
            path[1] = choice[2][path[2]];
        }
        __syncthreads();

        if (tid < 256) {
            const int i = tid >> 4, j = tid & 15;
            int idx = c_off[0] + path[1];
            M[tid] = lw[(size_t)idx * 256 + i * 16 + j];
            if (j == 0) cv[i] = lb[idx * 16 + i];
        }
        __syncthreads();
        for (int l = 2; l <= 4; l++) {
            float s = 0.f, sc = 0.f;
            const int i = tid >> 4, j = tid & 15;
            if (tid < 256) {
                int idx = c_off[l - 1] + path[l];
                const float* W = lw + (size_t)idx * 256;
#pragma unroll
                for (int k = 0; k < 16; k++)
                    s = fmaf(W[i * 16 + k], M[k * 16 + j], s);
                if (j == 0) {
                    sc = lb[idx * 16 + i];
#pragma unroll
                    for (int k = 0; k < 16; k++)
                        sc = fmaf(W[i * 16 + k], cv[k], sc);
                }
            }
            __syncthreads();
            if (tid < 256) {
                M[tid] = s;
                if ((tid & 15) == 0) cv[tid >> 4] = sc;
            }
            __syncthreads();
        }
        if (tid < 256) {
            g_M[b * 256 + tid] = M[tid];
            if ((tid & 15) == 0) g_cvec[b * VD + (tid >> 4)] = cv[tid >> 4];
        }
        __syncthreads();
    }
}

// ---------------------------------------------------------------------------
// Kernel 1: feats0 = root_w @ features + root_b, pooled partials, and (in the
// last-finishing block) the whole binomial tree.
// grid (NCHUNK1, B_) = 256 blocks x 256 threads.
// kg = t>>7 (k-half: 8 outputs), cg = (t>>6)&1 (channel half), lane = t&63
// (8 consecutive pixels). Pixel-paired f32x2 accumulators (8 k x 4 px-pairs).
// Weights in smem NON-duplicated (32 KB): warp reads its 8 weights as
// 2 broadcast LDS.128 and duplicates to (w,w) pairs with mov.b64 (ALU pipe).
// Dynamic smem: 32KB weights + 32KB cross-cg reduction buffer.
// ---------------------------------------------------------------------------
__global__ __launch_bounds__(256, 2)
void k_root(const float* __restrict__ feat,
            const float* __restrict__ rw,   // (16, 512)
            const float* __restrict__ rb,   // (16,)
            const float* __restrict__ lw,   // (14,16,16)
            const float* __restrict__ lb,   // (14,16)
            float* __restrict__ out)
{
    extern __shared__ float smem_dyn[];
    float* ws  = smem_dyn;                  // 512*16 floats = 32 KB (transposed)
    float* red = smem_dyn + CIN * VD;       // 16*512 floats = 32 KB

    const int t     = threadIdx.x;
    const int chunk = blockIdx.x;
    const int b     = blockIdx.y;
    const int kg    = t >> 7;               // k-half: outputs kg*8..kg*8+7
    const int cg    = (t >> 6) & 1;         // channel half
    const int lane  = t & 63;               // pixel lane (8 consecutive px)

    // ws[c*16+k] = rw[k*512+c]
    for (int i = t; i < CIN * VD; i += 256) {
        int c = i >> 4, k = i & 15;
        ws[i] = rw[k * CIN + c];
    }

    // Accumulators: 8 k-outputs x 4 pixel-pairs. Only cg0 seeds the bias.
    unsigned long long acc[8][4];
#pragma unroll
    for (int k = 0; k < 8; k++) {
        float bk = (cg == 0) ? __ldg(&rb[kg * 8 + k]) : 0.f;
        unsigned long long bp = pack2(bk, bk);
#pragma unroll
        for (int pp = 0; pp < 4; pp++) acc[k][pp] = bp;
    }
    __syncthreads();

    const float* gb = feat + ((size_t)b * CIN + cg * 256) * HW
                    + chunk * 512 + lane * 8;

    // Ping-pong over 128 groups of 2 channels (this thread's 256-ch half)
    ulonglong2 xA[2][2], xB[2][2];

#define LOAD_GRP(Xv, G)                                                        \
    {                                                                          \
        const ulonglong2* p0 = reinterpret_cast<const ulonglong2*>(            \
            gb + (size_t)(2 * (G)) * HW);                                      \
        const ulonglong2* p1 = reinterpret_cast<const ulonglong2*>(            \
            gb + (size_t)(2 * (G) + 1) * HW);                                  \
        Xv[0][0] = p0[0]; Xv[0][1] = p0[1];                                    \
        Xv[1][0] = p1[0]; Xv[1][1] = p1[1];                                    \
    }

#define COMP_GRP(Xv, G)                                                        \
    {                                                                          \
        _Pragma("unroll")                                                      \
        for (int j = 0; j < 2; j++) {                                          \
            const int c = cg * 256 + 2 * (G) + j;                              \
            const float4* wq = reinterpret_cast<const float4*>(                \
                ws + c * VD + kg * 8);                                         \
            float4 wa = wq[0], wb4 = wq[1];                                    \
            unsigned long long wp[8];                                          \
            wp[0] = pack2(wa.x, wa.x);  wp[1] = pack2(wa.y, wa.y);             \
            wp[2] = pack2(wa.z, wa.z);  wp[3] = pack2(wa.w, wa.w);             \
            wp[4] = pack2(wb4.x, wb4.x); wp[5] = pack2(wb4.y, wb4.y);          \
            wp[6] = pack2(wb4.z, wb4.z); wp[7] = pack2(wb4.w, wb4.w);          \
            unsigned long long xv[4] = {Xv[j][0].x, Xv[j][0].y,                \
                                        Xv[j][1].x, Xv[j][1].y};               \
            _Pragma("unroll")                                                  \
            for (int k = 0; k < 8; k++) {                                      \
                _Pragma("unroll")                                              \
                for (int pp = 0; pp < 4; pp++)                                 \
                    fma2(acc[k][pp], wp[k], xv[pp]);                           \
            }                                                                  \
        }                                                                      \
    }

    LOAD_GRP(xA, 0);
    for (int g = 0; g < 128; g += 2) {
        LOAD_GRP(xB, g + 1);
        COMP_GRP(xA, g);
        if (g + 2 < 128) LOAD_GRP(xA, g + 2);
        COMP_GRP(xB, g + 1);
    }
#undef LOAD_GRP
#undef COMP_GRP

    // Cross-cg reduction: cg1 parks its partials in smem
    if (cg == 1) {
#pragma unroll
        for (int k = 0; k < 8; k++) {
            float* r = red + (kg * 8 + k) * 512 + lane * 8;
            float v0, v1, v2, v3, v4, v5, v6, v7;
            unpack2(acc[k][0], v0, v1);
            unpack2(acc[k][1], v2, v3);
            unpack2(acc[k][2], v4, v5);
            unpack2(acc[k][3], v6, v7);
            *reinterpret_cast<float4*>(r)     = make_float4(v0, v1, v2, v3);
            *reinterpret_cast<float4*>(r + 4) = make_float4(v4, v5, v6, v7);
        }
    }
    __syncthreads();

    float ps[8];
    if (cg == 0) {
        float* ob = g_feats0 + (size_t)b * VD * HW + chunk * 512 + lane * 8;
#pragma unroll
        for (int k = 0; k < 8; k++) {
            const float* r = red + (kg * 8 + k) * 512 + lane * 8;
            float4 ra  = *reinterpret_cast<const float4*>(r);
            float4 rb4 = *reinterpret_cast<const float4*>(r + 4);
            float v0, v1, v2, v3, v4, v5, v6, v7;
            unpack2(acc[k][0], v0, v1);
            unpack2(acc[k][1], v2, v3);
            unpack2(acc[k][2], v4, v5);
            unpack2(acc[k][3], v6, v7);
            v0 += ra.x;  v1 += ra.y;  v2 += ra.z;  v3 += ra.w;
            v4 += rb4.x; v5 += rb4.y; v6 += rb4.z; v7 += rb4.w;
            float* o = ob + (size_t)(kg * 8 + k) * HW;
            *reinterpret_cast<float4*>(o)     = make_float4(v0, v1, v2, v3);
            *reinterpret_cast<float4*>(o + 4) = make_float4(v4, v5, v6, v7);
            ps[k] = ((v0 + v1) + (v2 + v3)) + ((v4 + v5) + (v6 + v7));
        }
#pragma unroll
        for (int off = 16; off > 0; off >>= 1) {
#pragma unroll
            for (int k = 0; k < 8; k++)
                ps[k] += __shfl_xor_sync(0xffffffffu, ps[k], off);
        }
    }
    __shared__ float wpool[2][2][8];        // [kg][warp-within-cg0][k]
    if (cg == 0 && (t & 31) == 0) {
        int wslot = (lane >> 5);
#pragma unroll
        for (int k = 0; k < 8; k++) wpool[kg][wslot][k] = ps[k];
    }
    __syncthreads();
    if (t < 16) {
        int kh = t >> 3, k = t & 7;
        float s = wpool[kh][0][k] + wpool[kh][1][k];
        g_pool_part[(b * NCHUNK1 + chunk) * VD + kh * 8 + k] = s;
    }

    // Last-finishing block runs the pooled binomial tree (deterministic)
    __shared__ int is_last;
    __syncthreads();
    if (t == 0) {
        __threadfence();
        int v = atomicAdd(&g_ctr_root, 1);
        is_last = (v == (int)(gridDim.x * gridDim.y) - 1);
    }
    __syncthreads();
    if (is_last) {
        tree_body(lw, lb, out, t);
        if (t == 0) g_ctr_root = 0;
    }
}

// ---------------------------------------------------------------------------
// Kernel 2: per-pixel selected feature -> normalize -> MLP(64) -> scalar sum,
// with fused finalization in the last block (threadfence + counter).
// grid: (NCHUNK3, B_), block: 256 (1 pixel/thread)
// ---------------------------------------------------------------------------
__global__ __launch_bounds__(256)
void k_mant(const float* __restrict__ m1w,  // (64,16)
            const float* __restrict__ m1b,  // (64,)
            const float* __restrict__ m2w,  // (1,64)
            const float* __restrict__ m2b,  // (1,)
            float* __restrict__ out)
{
    __shared__ float Ms[256], cs[VD], w1[64 * VD], b1[64], w2[64];
    __shared__ int is_last;
    const int tid   = threadIdx.x;
    const int chunk = blockIdx.x;
    const int b     = blockIdx.y;

    Ms[tid] = g_M[b * 256 + tid];
    if (tid < VD) cs[tid] = g_cvec[b * VD + tid];
    for (int idx = tid; idx < 64 * VD; idx += 256) w1[idx] = m1w[idx];
    if (tid < 64) { b1[tid] = m1b[tid]; w2[tid] = m2w[tid]; }
    __syncthreads();

    const int p = chunk * 256 + tid;
    const float* f0 = g_feats0 + (size_t)b * VD * HW + p;

    float x[VD];
#pragma unroll
    for (int k = 0; k < VD; k++) x[k] = f0[(size_t)k * HW];

    float v[VD];
#pragma unroll
    for (int i = 0; i < VD; i++) {
        float s = cs[i];
#pragma unroll
        for (int k = 0; k < VD; k++) s = fmaf(Ms[i * VD + k], x[k], s);
        v[i] = s;
    }
    float nrm = 0.f;
#pragma unroll
    for (int i = 0; i < VD; i++) nrm = fmaf(v[i], v[i], nrm);
    float inv = 1.0f / (sqrtf(nrm) + 1e-8f);
    float u[VD];
#pragma unroll
    for (int k = 0; k < VD; k++) u[k] = v[k] * inv;

    float s2 = 0.f;
#pragma unroll 4
    for (int jj = 0; jj < 64; jj++) {
        float t = b1[jj];
#pragma unroll
        for (int k = 0; k < VD; k++) t = fmaf(w1[jj * VD + k], u[k], t);
        t = fmaxf(t, 0.f);
        s2 = fmaf(w2[jj], t, s2);
    }

#pragma unroll
    for (int off = 16; off > 0; off >>= 1)
        s2 += __shfl_xor_sync(0xffffffffu, s2, off);
    __shared__ float rs[8];
    int wid = tid >> 5, lane = tid & 31;
    if (lane == 0) rs[wid] = s2;
    __syncthreads();
    if (tid == 0) {
        float t = ((rs[0] + rs[1]) + (rs[2] + rs[3])) +
                  ((rs[4] + rs[5]) + (rs[6] + rs[7]));
        g_mpart[b * NCHUNK3 + chunk] = t;
    }

    if (tid == 0) {
        __threadfence();
        int v2 = atomicAdd(&g_ctr_mant, 1);
        is_last = (v2 == (int)(gridDim.x * gridDim.y) - 1);
    }
    __syncthreads();
    if (is_last) {
        if (tid < B_) {
            float s = 0.f;
#pragma unroll
            for (int c = 0; c < NCHUNK3; c++) s += g_mpart[tid * NCHUNK3 + c];
            float mr = s * (1.0f / (float)HW) + m2b[0];
            float sig = 1.0f / (1.0f + expf(-mr));
            out[160 + tid] = sig * 0.75f + 0.75f;
        }
        if (tid == 0) g_ctr_mant = 0;
    }
}

// ---------------------------------------------------------------------------
extern "C" void kernel_launch(void* const* d_in, const int* in_sizes, int n_in,
                              void* d_out, int out_size)
{
    const float* features = (const float*)d_in[0];
    const float* root_w   = (const float*)d_in[1];
    const float* root_b   = (const float*)d_in[2];
    const float* level_w  = (const float*)d_in[3];
    const float* level_b  = (const float*)d_in[4];
    const float* m1_w     = (const float*)d_in[5];
    const float* m1_b     = (const float*)d_in[6];
    const float* m2_w     = (const float*)d_in[7];
    const float* m2_b     = (const float*)d_in[8];
    float* out = (float*)d_out;

    const int smem_root = CIN * VD * 4 + VD * 512 * 4;  // 32KB + 32KB = 64KB
    cudaFuncSetAttribute(k_root, cudaFuncAttributeMaxDynamicSharedMemorySize,
                         smem_root);

    dim3 g1(NCHUNK1, B_);
    k_root<<<g1, 256, smem_root>>>(features, root_w, root_b,
                                   level_w, level_b, out);

    dim3 g3(NCHUNK3, B_);
    k_mant<<<g3, 256>>>(m1_w, m1_b, m2_w, m2_b, out);
}

// round 11
// speedup vs baseline: 2.2341x; 2.2341x over previous
#include <cuda_runtime.h>
#include <cuda_bf16.h>
#include <stdint.h>
#include <math.h>

// Problem constants
#define B_      32
#define CIN     512
#define HW      4096          // 64*64
#define VD      16
#define NCHUNK1 8             // pixel chunks per image in k_root (512 px each)
#define NCHUNK3 8             // chunks per image in k_mant (512 px each)
#define NST     6             // cp.async pipeline depth
#define CPS     4             // channels per stage
#define NSTAGES (CIN / CPS)   // 128 stage iterations

// Scratch (device globals; no allocation allowed)
__device__ float g_feats0[B_ * VD * HW];          // 8 MB, layout [b][k][pixel]
__device__ float g_pool_part[B_ * NCHUNK1 * VD];  // per-chunk pooled partial sums
__device__ float g_M[B_ * VD * VD];               // composed path matrix per batch
__device__ float g_cvec[B_ * VD];                 // composed path bias per batch
__device__ float g_mpart[B_ * NCHUNK3];           // mantissa partial sums
__device__ int   g_ctr_mant;                      // k_mant completion counter

__constant__ int c_off[4] = {0, 2, 5, 9};         // LEVEL_OFFSETS

// ---- f32x2 packed helpers (Blackwell FFMA2, PTX-only) ----------------------
__device__ __forceinline__ unsigned long long bcast2(float w) {
    unsigned long long r;
    asm("mov.b64 %0, {%1, %1};" : "=l"(r) : "f"(w));
    return r;
}
__device__ __forceinline__ void fma2(unsigned long long& d,
                                     unsigned long long a,
                                     unsigned long long b) {
    asm("fma.rn.f32x2 %0, %1, %2, %0;" : "+l"(d) : "l"(a), "l"(b));
}
__device__ __forceinline__ void unpack2(unsigned long long p, float& lo, float& hi) {
    asm("mov.b64 {%0, %1}, %2;" : "=f"(lo), "=f"(hi) : "l"(p));
}
__device__ __forceinline__ void cp_async16(unsigned int saddr, const void* gptr) {
    asm volatile("cp.async.cg.shared.global [%0], [%1], 16;"
                 :: "r"(saddr), "l"(gptr) : "memory");
}

// ---------------------------------------------------------------------------
// Kernel 1: feats0 = root_w @ features + root_b, plus pooled partial sums.
// (R6 configuration — best measured.)  grid (NCHUNK1, B_), 128 threads.
// kg = t>>6 (k-half), lane = t&63 (8 consecutive pixels). cp.async 6-stage
// pipeline; weights in smem (broadcast LDS -> packed pairs); FFMA2 compute.
// Dynamic smem: [0,32KB) weights ws[c][k], [32KB, +NST*8KB) stage buffers.
// ---------------------------------------------------------------------------
__global__ __launch_bounds__(128, 2)
void k_root(const float* __restrict__ feat,
            const float* __restrict__ rw,   // (16, 512)
            const float* __restrict__ rb)   // (16,)
{
    extern __shared__ float smem_dyn[];
    float* ws   = smem_dyn;                 // 512*16 floats = 32 KB
    float* stg  = smem_dyn + CIN * VD;      // NST stages of 4*512 floats

    const int t     = threadIdx.x;
    const int chunk = blockIdx.x;
    const int b     = blockIdx.y;
    const int kg    = t >> 6;               // 0 or 1 (k-half)
    const int lane  = t & 63;               // pixel lane

    const float* gbase = feat + (size_t)b * CIN * HW + chunk * 512;

    // Prologue: start the cp.async pipeline immediately (stages 0..NST-2)
    unsigned int stg_s = (unsigned int)__cvta_generic_to_shared(stg);
#pragma unroll
    for (int s = 0; s < NST - 1; s++) {
        const float* g = gbase + (size_t)(s * CPS) * HW + t * 4;
        unsigned int d = stg_s + (unsigned int)(s) * (CPS * 512 * 4) + t * 16;
#pragma unroll
        for (int j = 0; j < CPS; j++)
            cp_async16(d + j * 2048, g + (size_t)j * HW);
        asm volatile("cp.async.commit_group;" ::: "memory");
    }

    // Stage weights transposed into shared while the pipeline fills:
    // ws[c*16+k] = rw[k*512+c]
    for (int i = t; i < CIN * VD; i += 128) {
        int c = i >> 4, k = i & 15;
        ws[i] = rw[k * CIN + c];
    }

    // Accumulators: 8 k-outputs x 4 pixel-pairs, initialized with bias
    unsigned long long acc[8][4];
#pragma unroll
    for (int k = 0; k < 8; k++) {
        unsigned long long bk = bcast2(__ldg(&rb[kg * 8 + k]));
#pragma unroll
        for (int pp = 0; pp < 4; pp++) acc[k][pp] = bk;
    }

    // Main pipeline loop over 128 stages of 4 channels
    for (int cs = 0; cs < NSTAGES; cs++) {
        asm volatile("cp.async.wait_group %0;" :: "n"(NST - 2) : "memory");
        __syncthreads();

        const int slot = cs % NST;
        const float* sb = stg + slot * (CPS * 512);
        const int cbase = cs * CPS;
#pragma unroll
        for (int j = 0; j < CPS; j++) {
            const float* wrow = ws + (cbase + j) * VD + kg * 8;
            float4 wa = *reinterpret_cast<const float4*>(wrow);
            float4 wb = *reinterpret_cast<const float4*>(wrow + 4);
            unsigned long long wp[8];
            wp[0] = bcast2(wa.x); wp[1] = bcast2(wa.y);
            wp[2] = bcast2(wa.z); wp[3] = bcast2(wa.w);
            wp[4] = bcast2(wb.x); wp[5] = bcast2(wb.y);
            wp[6] = bcast2(wb.z); wp[7] = bcast2(wb.w);

            const float* xs = sb + j * 512 + lane * 8;
            const unsigned long long* xp =
                reinterpret_cast<const unsigned long long*>(xs);
            unsigned long long x0 = xp[0], x1 = xp[1], x2 = xp[2], x3 = xp[3];
#pragma unroll
            for (int k = 0; k < 8; k++) {
                fma2(acc[k][0], wp[k], x0);
                fma2(acc[k][1], wp[k], x1);
                fma2(acc[k][2], wp[k], x2);
                fma2(acc[k][3], wp[k], x3);
            }
        }
        __syncthreads();

        // Issue next stage
        int ns = cs + NST - 1;
        if (ns < NSTAGES) {
            const float* g = gbase + (size_t)(ns * CPS) * HW + t * 4;
            unsigned int d = stg_s + (unsigned int)(ns % NST) * (CPS * 512 * 4) + t * 16;
#pragma unroll
            for (int j = 0; j < CPS; j++)
                cp_async16(d + j * 2048, g + (size_t)j * HW);
        }
        asm volatile("cp.async.commit_group;" ::: "memory");
    }

    // Epilogue: store feats0 + pooled partials
    float* ob = g_feats0 + (size_t)b * VD * HW + chunk * 512 + lane * 8;
    float ps[8];
#pragma unroll
    for (int k = 0; k < 8; k++) {
        float v0, v1, v2, v3, v4, v5, v6, v7;
        unpack2(acc[k][0], v0, v1);
        unpack2(acc[k][1], v2, v3);
        unpack2(acc[k][2], v4, v5);
        unpack2(acc[k][3], v6, v7);
        float* o = ob + (size_t)(kg * 8 + k) * HW;
        *reinterpret_cast<float4*>(o)     = make_float4(v0, v1, v2, v3);
        *reinterpret_cast<float4*>(o + 4) = make_float4(v4, v5, v6, v7);
        ps[k] = ((v0 + v1) + (v2 + v3)) + ((v4 + v5) + (v6 + v7));
    }

#pragma unroll
    for (int off = 16; off > 0; off >>= 1) {
#pragma unroll
        for (int k = 0; k < 8; k++)
            ps[k] += __shfl_xor_sync(0xffffffffu, ps[k], off);
    }
    __shared__ float wpool[4][8];
    const int wid = t >> 5, lid = t & 31;
    if (lid == 0) {
#pragma unroll
        for (int k = 0; k < 8; k++) wpool[wid][k] = ps[k];
    }
    __syncthreads();
    if (t < 16) {
        int kh = t >> 3, k = t & 7;
        float s = wpool[kh * 2][k] + wpool[kh * 2 + 1][k];
        g_pool_part[(b * NCHUNK1 + chunk) * VD + kh * 8 + k] = s;
    }
}

// ---------------------------------------------------------------------------
// Kernel 2: pooled binomial tree per batch (R6 verbatim). grid: B_, block: 256
// ---------------------------------------------------------------------------
__global__ __launch_bounds__(256)
void k_tree(const float* __restrict__ lw,   // (14,16,16)
            const float* __restrict__ lb,   // (14,16)
            float* __restrict__ out)
{
    const int b   = blockIdx.x;
    const int tid = threadIdx.x;

    __shared__ float P[5][VD], Pn[5][VD];
    __shared__ float norms[5];
    __shared__ int   choice[5][5];
    __shared__ int   path[5];
    __shared__ float M[VD * VD], cv[VD];

    if (tid < VD) {
        float s = 0.f;
#pragma unroll
        for (int c = 0; c < NCHUNK1; c++)
            s += g_pool_part[(b * NCHUNK1 + c) * VD + tid];
        P[0][tid] = s * (1.0f / (float)HW);
    }
    __syncthreads();

    int ncur = 1;
    for (int level = 1; level <= 4; level++) {
        const int off = c_off[level - 1];
        const int nn  = level + 1;
        if (tid < ncur) {
            float s = 0.f;
#pragma unroll
            for (int k = 0; k < VD; k++) s += P[tid][k] * P[tid][k];
            norms[tid] = sqrtf(s);
        }
        __syncthreads();
        if (tid < nn) {
            int pl = tid - 1; if (pl < 0) pl = 0;
            int pr = tid;     if (pr > level - 1) pr = level - 1;
            int ch = pl;
            if (pl != pr && norms[pr] > norms[pl]) ch = pr;
            choice[level][tid] = ch;
        }
        __syncthreads();
        if (tid < nn * VD) {
            int node = tid >> 4, i = tid & 15;
            const float* W = lw + (size_t)(off + node) * VD * VD + i * VD;
            const float* par = P[choice[level][node]];
            float s = lb[(off + node) * VD + i];
#pragma unroll
            for (int k = 0; k < VD; k++) s = fmaf(W[k], par[k], s);
            Pn[node][i] = s;
        }
        __syncthreads();
        if (tid < nn * VD) P[tid >> 4][tid & 15] = Pn[tid >> 4][tid & 15];
        __syncthreads();
        ncur = nn;
    }

    if (tid < 5) {
        float s = 0.f;
#pragma unroll
        for (int k = 0; k < VD; k++) s += P[tid][k] * P[tid][k];
        norms[tid] = sqrtf(s);
        out[b * 5 + tid] = norms[tid];          // class_logits
    }
    __syncthreads();
    if (tid == 0) {
        int best = 0; float bv = norms[0];
        for (int j = 1; j < 5; j++)
            if (norms[j] > bv) { bv = norms[j]; best = j; }
        out[192 + b] = (float)best;             // selected_class
        path[4] = best;
        path[3] = choice[4][path[4]];
        path[2] = choice[3][path[3]];
        path[1] = choice[2][path[2]];
    }
    __syncthreads();

    const int i = tid >> 4, j = tid & 15;
    {
        int idx = c_off[0] + path[1];
        M[tid] = lw[(size_t)idx * 256 + i * 16 + j];
        if (j == 0) cv[i] = lb[idx * 16 + i];
    }
    __syncthreads();
    for (int l = 2; l <= 4; l++) {
        int idx = c_off[l - 1] + path[l];
        const float* W = lw + (size_t)idx * 256;
        float s = 0.f;
#pragma unroll
        for (int k = 0; k < 16; k++) s = fmaf(W[i * 16 + k], M[k * 16 + j], s);
        float sc = 0.f;
        if (j == 0) {
            sc = lb[idx * 16 + i];
#pragma unroll
            for (int k = 0; k < 16; k++) sc = fmaf(W[i * 16 + k], cv[k], sc);
        }
        __syncthreads();
        M[tid] = s;
        if (j == 0) cv[i] = sc;
        __syncthreads();
    }
    g_M[b * 256 + tid] = M[tid];
    if (j == 0) g_cvec[b * VD + i] = cv[i];
}

// ---------------------------------------------------------------------------
// Kernel 3: selected feature -> normalize -> MLP(64) -> scalar mean, TWO
// pixels per thread (halves smem-broadcast traffic for Ms/w1), fused
// finalization in the last block.  grid: (NCHUNK3, B_), block: 256.
// ---------------------------------------------------------------------------
__global__ __launch_bounds__(256)
void k_mant(const float* __restrict__ m1w,  // (64,16)
            const float* __restrict__ m1b,  // (64,)
            const float* __restrict__ m2w,  // (1,64)
            const float* __restrict__ m2b,  // (1,)
            float* __restrict__ out)
{
    __shared__ float Ms[256], cs[VD], w1[64 * VD], b1[64], w2[64];
    __shared__ int is_last;
    const int tid   = threadIdx.x;
    const int chunk = blockIdx.x;
    const int b     = blockIdx.y;

    Ms[tid] = g_M[b * 256 + tid];
    if (tid < VD) cs[tid] = g_cvec[b * VD + tid];
    for (int idx = tid; idx < 64 * VD; idx += 256) w1[idx] = m1w[idx];
    if (tid < 64) { b1[tid] = m1b[tid]; w2[tid] = m2w[tid]; }
    __syncthreads();

    const int p = chunk * 512 + tid * 2;    // two consecutive pixels
    const float* f0 = g_feats0 + (size_t)b * VD * HW + p;

    float2 x[VD];
#pragma unroll
    for (int k = 0; k < VD; k++)
        x[k] = *reinterpret_cast<const float2*>(f0 + (size_t)k * HW);

    float v0[VD], v1[VD];
#pragma unroll
    for (int i = 0; i < VD; i++) {
        float s0 = cs[i], s1 = cs[i];
#pragma unroll
        for (int k = 0; k < VD; k++) {
            float m = Ms[i * VD + k];
            s0 = fmaf(m, x[k].x, s0);
            s1 = fmaf(m, x[k].y, s1);
        }
        v0[i] = s0; v1[i] = s1;
    }
    float n0 = 0.f, n1 = 0.f;
#pragma unroll
    for (int i = 0; i < VD; i++) {
        n0 = fmaf(v0[i], v0[i], n0);
        n1 = fmaf(v1[i], v1[i], n1);
    }
    float i0 = 1.0f / (sqrtf(n0) + 1e-8f);
    float i1 = 1.0f / (sqrtf(n1) + 1e-8f);
#pragma unroll
    for (int k = 0; k < VD; k++) { v0[k] *= i0; v1[k] *= i1; }

    float s20 = 0.f, s21 = 0.f;
#pragma unroll 4
    for (int jj = 0; jj < 64; jj++) {
        float t0 = b1[jj], t1 = t0;
#pragma unroll
        for (int k = 0; k < VD; k++) {
            float w = w1[jj * VD + k];
            t0 = fmaf(w, v0[k], t0);
            t1 = fmaf(w, v1[k], t1);
        }
        t0 = fmaxf(t0, 0.f);
        t1 = fmaxf(t1, 0.f);
        float w2j = w2[jj];
        s20 = fmaf(w2j, t0, s20);
        s21 = fmaf(w2j, t1, s21);
    }
    float s2 = s20 + s21;

#pragma unroll
    for (int off = 16; off > 0; off >>= 1)
        s2 += __shfl_xor_sync(0xffffffffu, s2, off);
    __shared__ float rs[8];
    int wid = tid >> 5, lane = tid & 31;
    if (lane == 0) rs[wid] = s2;
    __syncthreads();
    if (tid == 0) {
        float t = ((rs[0] + rs[1]) + (rs[2] + rs[3])) +
                  ((rs[4] + rs[5]) + (rs[6] + rs[7]));
        g_mpart[b * NCHUNK3 + chunk] = t;
    }

    // Last-block finalization (deterministic fixed-order sums)
    if (tid == 0) {
        __threadfence();
        int v2 = atomicAdd(&g_ctr_mant, 1);
        is_last = (v2 == (int)(gridDim.x * gridDim.y) - 1);
    }
    __syncthreads();
    if (is_last) {
        if (tid < B_) {
            float s = 0.f;
#pragma unroll
            for (int c = 0; c < NCHUNK3; c++) s += g_mpart[tid * NCHUNK3 + c];
            float mr = s * (1.0f / (float)HW) + m2b[0];
            float sig = 1.0f / (1.0f + expf(-mr));
            out[160 + tid] = sig * 0.75f + 0.75f;
        }
        if (tid == 0) g_ctr_mant = 0;   // reset for next graph replay
    }
}

// ---------------------------------------------------------------------------
extern "C" void kernel_launch(void* const* d_in, const int* in_sizes, int n_in,
                              void* d_out, int out_size)
{
    const float* features = (const float*)d_in[0];
    const float* root_w   = (const float*)d_in[1];
    const float* root_b   = (const float*)d_in[2];
    const float* level_w  = (const float*)d_in[3];
    const float* level_b  = (const float*)d_in[4];
    const float* m1_w     = (const float*)d_in[5];
    const float* m1_b     = (const float*)d_in[6];
    const float* m2_w     = (const float*)d_in[7];
    const float* m2_b     = (const float*)d_in[8];
    float* out = (float*)d_out;

    const int smem_root = CIN * VD * 4 + NST * CPS * 512 * 4;  // 32KB + 48KB
    cudaFuncSetAttribute(k_root, cudaFuncAttributeMaxDynamicSharedMemorySize,
                         smem_root);

    dim3 g1(NCHUNK1, B_);
    k_root<<<g1, 128, smem_root>>>(features, root_w, root_b);

    k_tree<<<B_, 256>>>(level_w, level_b, out);

    dim3 g3(NCHUNK3, B_);
    k_mant<<<g3, 256>>>(m1_w, m1_b, m2_w, m2_b, out);
}